// round 11
// baseline (speedup 1.0000x reference)
#include <cuda_runtime.h>
#include <cuda_bf16.h>
#include <cuda_fp16.h>
#include <cstdint>

#define NN    10000
#define EMAXX 160000
#define ETOT  (EMAXX + NN)

// ---------------- device scratch (no allocations allowed) ----------------
__device__ int   g_is64;
__device__ int   g_deg[NN];
__device__ float g_dinv[NN];
__device__ int   g_off[NN + 1];
__device__ int   g_cur[NN];
__device__ int2  g_edge[ETOT];                    // {row, __float_as_int(norm)}
__device__ __half g_h16[(size_t)NN * 512];        // fp16 activations (GEMM out, relu'd)
__device__ __half g_af[(size_t)NN * 512];         // A fp16 (SpMM out)
__device__ __half g_wh[4 * 512 * 512];            // W^T fp16, [N rows][K cols]

__device__ __forceinline__ int ld_idx(const void* p, long long i) {
    if (g_is64) return (int)((const long long*)p)[i];
    return ((const int*)p)[i];
}

// ---------------- preprocessing ----------------
__global__ void k_detect(const void* ei, int E) {
    if (threadIdx.x < 32) {
        const long long* p = (const long long*)ei;
        int lim = (E < 64) ? E : 64;
        int bad = 0;
        for (int j = threadIdx.x; j < lim; j += 32) {
            long long v = p[j];
            bad |= (v < 0 || v >= NN);
        }
        unsigned m = __ballot_sync(0xFFFFFFFFu, bad);
        if (threadIdx.x == 0) g_is64 = (m == 0);
    }
}
__global__ void k_deg(const void* ei, int E) {
    int e = blockIdx.x * blockDim.x + threadIdx.x;
    if (e < E) atomicAdd(&g_deg[ld_idx(ei, (long long)E + e)], 1);
}
// single-block scan of (deg+1) -> off, plus dinv   (+1 = self loop)
__global__ void k_scan() {
    __shared__ int s[1024];
    const int CH = 10;
    int t = threadIdx.x;
    int base = t * CH, loc[CH], sum = 0;
#pragma unroll
    for (int j = 0; j < CH; j++) {
        int idx = base + j;
        int v = (idx < NN) ? (g_deg[idx] + 1) : 0;
        if (idx < NN) g_dinv[idx] = rsqrtf((float)v);
        loc[j] = sum; sum += v;
    }
    s[t] = sum;
    __syncthreads();
    for (int d = 1; d < 1024; d <<= 1) {
        int v = (t >= d) ? s[t - d] : 0;
        __syncthreads();
        s[t] += v;
        __syncthreads();
    }
    int excl = (t > 0) ? s[t - 1] : 0;
#pragma unroll
    for (int j = 0; j < CH; j++) {
        int idx = base + j;
        if (idx < NN) g_off[idx] = excl + loc[j];
    }
    if (t == 0) g_off[NN] = s[1023];
}
__global__ void k_fill(const void* ei, int E) {
    int e = blockIdx.x * blockDim.x + threadIdx.x;
    int tot = E + NN;
    if (e >= tot) return;
    int r, c;
    if (e < E) { r = ld_idx(ei, e); c = ld_idx(ei, (long long)E + e); }
    else { r = e - E; c = r; }
    int p = atomicAdd(&g_cur[c], 1);
    int idx = g_off[c] + p;
    g_edge[idx] = make_int2(r, __float_as_int(g_dinv[r] * g_dinv[c]));
}

// all 4 weights: W [K,512] fp32 -> Wt fp16 [512][K] (tiled transpose)
__global__ void k_wconv_all(const float* __restrict__ W1, const float* __restrict__ W2,
                            const float* __restrict__ W3, const float* __restrict__ W4,
                            __half* __restrict__ whB) {
    __shared__ float t[32][33];
    int l = blockIdx.z;
    const float* W = (l == 0) ? W1 : (l == 1) ? W2 : (l == 2) ? W3 : W4;
    int K = (l == 0) ? 256 : 512;
    int k0 = blockIdx.x * 32, n0 = blockIdx.y * 32;
    if (k0 >= K) return;
    __half* wh = whB + (size_t)l * 512 * 512;
    int tx = threadIdx.x, ty = threadIdx.y;
    t[ty][tx] = W[(size_t)(k0 + ty) * 512 + n0 + tx];
    __syncthreads();
    wh[(size_t)(n0 + ty) * K + k0 + tx] = __float2half_rn(t[tx][ty]);
}

// ---------------- SpMM: acc fp32, write fp16 ----------------
__device__ __forceinline__ uint32_t packh2(float a, float b) {
    __half2 t = __floats2half2_rn(a, b);
    return *(uint32_t*)&t;
}
// layer 1: fp32 input, FD=256, 64 threads
__global__ void k_spmm_f32in(const float* __restrict__ h, __half* __restrict__ af) {
    const int FD = 256, V = FD / 4;
    int node = blockIdx.x;
    int tid  = threadIdx.x;
    int s = g_off[node], e = g_off[node + 1];
    const float4* h4 = (const float4*)h;
    float4 acc = make_float4(0.f, 0.f, 0.f, 0.f);
    int i = s;
    for (; i + 4 <= e; i += 4) {
        int2 e0 = g_edge[i],     e1 = g_edge[i + 1];
        int2 e2 = g_edge[i + 2], e3 = g_edge[i + 3];
        float w0 = __int_as_float(e0.y), w1 = __int_as_float(e1.y);
        float w2 = __int_as_float(e2.y), w3 = __int_as_float(e3.y);
        float4 v0 = h4[(size_t)e0.x * V + tid];
        float4 v1 = h4[(size_t)e1.x * V + tid];
        float4 v2 = h4[(size_t)e2.x * V + tid];
        float4 v3 = h4[(size_t)e3.x * V + tid];
        acc.x += w0 * v0.x; acc.y += w0 * v0.y; acc.z += w0 * v0.z; acc.w += w0 * v0.w;
        acc.x += w1 * v1.x; acc.y += w1 * v1.y; acc.z += w1 * v1.z; acc.w += w1 * v1.w;
        acc.x += w2 * v2.x; acc.y += w2 * v2.y; acc.z += w2 * v2.z; acc.w += w2 * v2.w;
        acc.x += w3 * v3.x; acc.y += w3 * v3.y; acc.z += w3 * v3.z; acc.w += w3 * v3.w;
    }
    for (; i < e; i++) {
        int2 e0 = g_edge[i];
        float w = __int_as_float(e0.y);
        float4 v = h4[(size_t)e0.x * V + tid];
        acc.x += w * v.x; acc.y += w * v.y; acc.z += w * v.z; acc.w += w * v.w;
    }
    uint2 u;
    u.x = packh2(acc.x, acc.y);
    u.y = packh2(acc.z, acc.w);
    *(uint2*)(af + (size_t)node * FD + tid * 4) = u;
}
// layers 2-4: fp16 input, FD=512, 128 threads (8B gather per thread)
__global__ void k_spmm_f16in(const __half* __restrict__ h, __half* __restrict__ af) {
    const int FD = 512, V = FD / 4;                // uint2 = 4 halves
    int node = blockIdx.x;
    int tid  = threadIdx.x;
    int s = g_off[node], e = g_off[node + 1];
    const uint2* h4 = (const uint2*)h;
    float4 acc = make_float4(0.f, 0.f, 0.f, 0.f);
    int i = s;
    for (; i + 4 <= e; i += 4) {
        int2 e0 = g_edge[i],     e1 = g_edge[i + 1];
        int2 e2 = g_edge[i + 2], e3 = g_edge[i + 3];
        float w0 = __int_as_float(e0.y), w1 = __int_as_float(e1.y);
        float w2 = __int_as_float(e2.y), w3 = __int_as_float(e3.y);
        uint2 u0 = h4[(size_t)e0.x * V + tid];
        uint2 u1 = h4[(size_t)e1.x * V + tid];
        uint2 u2 = h4[(size_t)e2.x * V + tid];
        uint2 u3 = h4[(size_t)e3.x * V + tid];
        float2 a0 = __half22float2(*(__half2*)&u0.x), b0 = __half22float2(*(__half2*)&u0.y);
        float2 a1 = __half22float2(*(__half2*)&u1.x), b1 = __half22float2(*(__half2*)&u1.y);
        float2 a2 = __half22float2(*(__half2*)&u2.x), b2 = __half22float2(*(__half2*)&u2.y);
        float2 a3 = __half22float2(*(__half2*)&u3.x), b3 = __half22float2(*(__half2*)&u3.y);
        acc.x += w0 * a0.x; acc.y += w0 * a0.y; acc.z += w0 * b0.x; acc.w += w0 * b0.y;
        acc.x += w1 * a1.x; acc.y += w1 * a1.y; acc.z += w1 * b1.x; acc.w += w1 * b1.y;
        acc.x += w2 * a2.x; acc.y += w2 * a2.y; acc.z += w2 * b2.x; acc.w += w2 * b2.y;
        acc.x += w3 * a3.x; acc.y += w3 * a3.y; acc.z += w3 * b3.x; acc.w += w3 * b3.y;
    }
    for (; i < e; i++) {
        int2 e0 = g_edge[i];
        float w = __int_as_float(e0.y);
        uint2 u0 = h4[(size_t)e0.x * V + tid];
        float2 a0 = __half22float2(*(__half2*)&u0.x), b0 = __half22float2(*(__half2*)&u0.y);
        acc.x += w * a0.x; acc.y += w * a0.y; acc.z += w * b0.x; acc.w += w * b0.y;
    }
    uint2 u;
    u.x = packh2(acc.x, acc.y);
    u.y = packh2(acc.z, acc.w);
    *(uint2*)(af + (size_t)node * FD + tid * 4) = u;
}

// ---------------- HMMA helpers ----------------
__device__ __forceinline__ uint32_t smem_u32(const void* p) {
    uint32_t a;
    asm("{ .reg .u64 t; cvta.to.shared.u64 t, %1; cvt.u32.u64 %0, t; }" : "=r"(a) : "l"(p));
    return a;
}
#define LDSM_X4(r0, r1, r2, r3, addr) \
    asm volatile("ldmatrix.sync.aligned.m8n8.x4.shared.b16 {%0,%1,%2,%3}, [%4];" \
        : "=r"(r0), "=r"(r1), "=r"(r2), "=r"(r3) : "r"(addr))
#define MMA16816F(d, a0, a1, a2, a3, b0, b1) \
    asm volatile("mma.sync.aligned.m16n8k16.row.col.f32.f16.f16.f32 " \
        "{%0,%1,%2,%3}, {%4,%5,%6,%7}, {%8,%9}, {%0,%1,%2,%3};" \
        : "+f"((d)[0]), "+f"((d)[1]), "+f"((d)[2]), "+f"((d)[3]) \
        : "r"(a0), "r"(a1), "r"(a2), "r"(a3), "r"(b0), "r"(b1))
#define CP_ASYNC16(dst, src, sz) \
    asm volatile("cp.async.cg.shared.global [%0], [%1], 16, %2;" \
        :: "r"(dst), "l"(src), "r"(sz) : "memory")
#define CP_COMMIT() asm volatile("cp.async.commit_group;" ::: "memory")
#define CP_WAIT(n)  asm volatile("cp.async.wait_group %0;" :: "n"(n) : "memory")

// ---------------- fp16 single-pass HMMA GEMM, K-chunk 64, 3-stage -----------
// layers 1-3 (OUT16=1): h16 = relu(A @ Wh^T + bias) fp16
// layer 4   (OUT16=0): out = A @ Wh^T + bias fp32
#define SPAD 72   // padded smem row stride (fp16 elems) for 64-wide K chunk
template <int K, int OUT16>
__global__ void __launch_bounds__(256, 2)
k_gemm_mma(const __half* __restrict__ Af, const __half* __restrict__ Wh,
           const float* __restrict__ bias, void* __restrict__ Cout) {
    extern __shared__ __half sm[];
    const int M = NN;
    const int NC = K / 64;                        // 4 or 8
    const int TILE = 128 * SPAD;
    const int STAGE = 2 * TILE;                   // Af, Wh

    int tid = threadIdx.x;
    int wid = tid >> 5, lane = tid & 31;
    int wm = wid & 3, wn = wid >> 2;              // warp grid 4(M) x 2(N)
    int bx = blockIdx.x, by = blockIdx.y;

    float acc[2][8][4];
#pragma unroll
    for (int i = 0; i < 2; i++)
#pragma unroll
        for (int j = 0; j < 8; j++)
#pragma unroll
            for (int q = 0; q < 4; q++) acc[i][j][q] = 0.f;

    auto stage_load = [&](int st, int k0) {
        __half* dst = sm + st * STAGE;
#pragma unroll
        for (int t = 0; t < 2; t++) {
            const __half* src = t ? Wh : Af;
            bool isA = (t == 0);
            int rowBase = isA ? by * 128 : bx * 128;
#pragma unroll
            for (int it = 0; it < 4; it++) {
                int idx = it * 256 + tid;
                int r = idx >> 3, kc = idx & 7;
                int gr = rowBase + r;
                uint32_t d = smem_u32(dst + t * TILE + r * SPAD + kc * 8);
                const __half* s = src + (size_t)gr * K + k0 + kc * 8;
                int sz = (!isA || gr < M) ? 16 : 0;
                CP_ASYNC16(d, s, sz);
            }
        }
    };

    stage_load(0, 0);
    CP_COMMIT();
    stage_load(1, 64);
    CP_COMMIT();

    for (int i = 0; i < NC; i++) {
        if (i + 2 < NC) { stage_load((i + 2) % 3, (i + 2) * 64); CP_COMMIT(); CP_WAIT(2); }
        else if (i + 1 < NC) CP_WAIT(1);
        else CP_WAIT(0);
        __syncthreads();

        __half* st = sm + (i % 3) * STAGE;
        uint32_t sAf = smem_u32(st);
        uint32_t sBh = smem_u32(st + TILE);

#pragma unroll
        for (int ks = 0; ks < 4; ks++) {
            int koff = ks * 16 + (lane >> 4) * 8;
            int arow = wm * 32 + (lane & 15);
            int brow = wn * 64 + (lane & 15);
            uint32_t ah[2][4];
#pragma unroll
            for (int mi = 0; mi < 2; mi++) {
                uint32_t ad = (uint32_t)(((arow + mi * 16) * SPAD + koff) * 2);
                LDSM_X4(ah[mi][0], ah[mi][1], ah[mi][2], ah[mi][3], sAf + ad);
            }
#pragma unroll
            for (int ni = 0; ni < 4; ni++) {
                uint32_t bd = (uint32_t)(((brow + ni * 16) * SPAD + koff) * 2);
                uint32_t bh[4];
                LDSM_X4(bh[0], bh[1], bh[2], bh[3], sBh + bd);
#pragma unroll
                for (int mi = 0; mi < 2; mi++) {
                    MMA16816F(acc[mi][ni * 2 + 0], ah[mi][0], ah[mi][1], ah[mi][2], ah[mi][3],
                              bh[0], bh[2]);
                    MMA16816F(acc[mi][ni * 2 + 1], ah[mi][0], ah[mi][1], ah[mi][2], ah[mi][3],
                              bh[1], bh[3]);
                }
            }
        }
        __syncthreads();
    }

    // epilogue
#pragma unroll
    for (int mi = 0; mi < 2; mi++) {
        int grow = by * 128 + wm * 32 + mi * 16 + (lane >> 2);
#pragma unroll
        for (int ni = 0; ni < 8; ni++) {
            int gcol = bx * 128 + wn * 64 + ni * 8 + (lane & 3) * 2;
            float bx0 = bias[gcol], bx1 = bias[gcol + 1];
            float2 v0, v1;
            v0.x = acc[mi][ni][0] + bx0; v0.y = acc[mi][ni][1] + bx1;
            v1.x = acc[mi][ni][2] + bx0; v1.y = acc[mi][ni][3] + bx1;
            if (OUT16) {
                v0.x = fmaxf(v0.x, 0.f); v0.y = fmaxf(v0.y, 0.f);
                v1.x = fmaxf(v1.x, 0.f); v1.y = fmaxf(v1.y, 0.f);
                __half* C16 = (__half*)Cout;
                if (grow < M)
                    *(__half2*)(C16 + (size_t)grow * 512 + gcol) = __floats2half2_rn(v0.x, v0.y);
                if (grow + 8 < M)
                    *(__half2*)(C16 + (size_t)(grow + 8) * 512 + gcol) = __floats2half2_rn(v1.x, v1.y);
            } else {
                float* C = (float*)Cout;
                if (grow < M)     *(float2*)(C + (size_t)grow * 512 + gcol) = v0;
                if (grow + 8 < M) *(float2*)(C + (size_t)(grow + 8) * 512 + gcol) = v1;
            }
        }
    }
}

// ---------------- launch ----------------
extern "C" void kernel_launch(void* const* d_in, const int* in_sizes, int n_in,
                              void* d_out, int out_size) {
    const float* x  = (const float*)d_in[0];
    const void*  ei = d_in[1];
    const float* W1 = (const float*)d_in[2];
    const float* b1 = (const float*)d_in[3];
    const float* W2 = (const float*)d_in[4];
    const float* b2 = (const float*)d_in[5];
    const float* W3 = (const float*)d_in[6];
    const float* b3 = (const float*)d_in[7];
    const float* W4 = (const float*)d_in[8];
    const float* b4 = (const float*)d_in[9];
    float* out = (float*)d_out;

    int E = in_sizes[1] / 2;

    __half *h16, *af, *wh;
    int *degp, *curp;
    cudaGetSymbolAddress((void**)&h16,  g_h16);
    cudaGetSymbolAddress((void**)&af,   g_af);
    cudaGetSymbolAddress((void**)&wh,   g_wh);
    cudaGetSymbolAddress((void**)&degp, g_deg);
    cudaGetSymbolAddress((void**)&curp, g_cur);

    const int GSMEM = 3 * 2 * 128 * SPAD * 2;   // 3 stages * 2 tiles = 110592 B
    static int attr_done = 0;
    if (!attr_done) {
        cudaFuncSetAttribute((const void*)k_gemm_mma<256, 1>, cudaFuncAttributeMaxDynamicSharedMemorySize, GSMEM);
        cudaFuncSetAttribute((const void*)k_gemm_mma<512, 1>, cudaFuncAttributeMaxDynamicSharedMemorySize, GSMEM);
        cudaFuncSetAttribute((const void*)k_gemm_mma<512, 0>, cudaFuncAttributeMaxDynamicSharedMemorySize, GSMEM);
        attr_done = 1;
    }

    // ---- preprocessing ----
    k_detect<<<1, 32>>>(ei, E);
    cudaMemsetAsync(degp, 0, NN * sizeof(int));
    cudaMemsetAsync(curp, 0, NN * sizeof(int));
    k_deg<<<(E + 255) / 256, 256>>>(ei, E);
    k_scan<<<1, 1024>>>();
    k_fill<<<(E + NN + 255) / 256, 256>>>(ei, E);
    k_wconv_all<<<dim3(16, 16, 4), dim3(32, 32)>>>(W1, W2, W3, W4, wh);

    dim3 ggrid(4, (NN + 127) / 128);

    // ---- layer 1 (K=256) ----
    k_spmm_f32in<<<NN, 64>>>(x, af);
    k_gemm_mma<256, 1><<<ggrid, 256, GSMEM>>>(af, wh + 0 * 512 * 512, b1, h16);
    // ---- layer 2 ----
    k_spmm_f16in<<<NN, 128>>>(h16, af);
    k_gemm_mma<512, 1><<<ggrid, 256, GSMEM>>>(af, wh + 1 * 512 * 512, b2, h16);
    // ---- layer 3 ----
    k_spmm_f16in<<<NN, 128>>>(h16, af);
    k_gemm_mma<512, 1><<<ggrid, 256, GSMEM>>>(af, wh + 2 * 512 * 512, b3, h16);
    // ---- layer 4 (no relu, fp32 to d_out) ----
    k_spmm_f16in<<<NN, 128>>>(h16, af);
    k_gemm_mma<512, 0><<<ggrid, 256, GSMEM>>>(af, wh + 3 * 512 * 512, b4, out);
}

// round 13
// speedup vs baseline: 1.0287x; 1.0287x over previous
#include <cuda_runtime.h>
#include <cuda_bf16.h>
#include <cuda_fp16.h>
#include <cstdint>

#define NN    10000
#define EMAXX 160000
#define ETOT  (EMAXX + NN)

// ---------------- device scratch (no allocations allowed) ----------------
__device__ int   g_is64;
__device__ int   g_deg[NN];
__device__ float g_dinv[NN];
__device__ int   g_off[NN + 1];
__device__ int   g_cur[NN];
__device__ int2  g_edge[ETOT];                    // {row, __float_as_int(norm)}
__device__ __half g_h16[(size_t)NN * 512];        // fp16 activations (GEMM out, relu'd)
__device__ __half g_af[(size_t)NN * 512];         // A fp16 (SpMM out)
__device__ __half g_wh[4 * 512 * 512];            // W^T fp16, [N rows][K cols]

__device__ __forceinline__ int ld_idx(const void* p, long long i) {
    if (g_is64) return (int)((const long long*)p)[i];
    return ((const int*)p)[i];
}

// ---------------- preprocessing ----------------
// fused: zero deg/cur + warp-parallel dtype detect (block 0, warp 0)
__global__ void k_init(const void* ei, int E) {
    int i = blockIdx.x * blockDim.x + threadIdx.x;
    if (i < NN) { g_deg[i] = 0; g_cur[i] = 0; }
    if (blockIdx.x == 0 && threadIdx.x < 32) {
        const long long* p = (const long long*)ei;
        int lim = (E < 64) ? E : 64;
        int bad = 0;
        for (int j = threadIdx.x; j < lim; j += 32) {
            long long v = p[j];
            bad |= (v < 0 || v >= NN);
        }
        unsigned m = __ballot_sync(0xFFFFFFFFu, bad);
        if (threadIdx.x == 0) g_is64 = (m == 0);
    }
}
__global__ void k_deg(const void* ei, int E) {
    int e = blockIdx.x * blockDim.x + threadIdx.x;
    if (e < E) atomicAdd(&g_deg[ld_idx(ei, (long long)E + e)], 1);
}
// single-block scan of (deg+1) -> off, plus dinv   (+1 = self loop)
__global__ void k_scan() {
    __shared__ int s[1024];
    const int CH = 10;
    int t = threadIdx.x;
    int base = t * CH, loc[CH], sum = 0;
#pragma unroll
    for (int j = 0; j < CH; j++) {
        int idx = base + j;
        int v = (idx < NN) ? (g_deg[idx] + 1) : 0;
        if (idx < NN) g_dinv[idx] = rsqrtf((float)v);
        loc[j] = sum; sum += v;
    }
    s[t] = sum;
    __syncthreads();
    for (int d = 1; d < 1024; d <<= 1) {
        int v = (t >= d) ? s[t - d] : 0;
        __syncthreads();
        s[t] += v;
        __syncthreads();
    }
    int excl = (t > 0) ? s[t - 1] : 0;
#pragma unroll
    for (int j = 0; j < CH; j++) {
        int idx = base + j;
        if (idx < NN) g_off[idx] = excl + loc[j];
    }
    if (t == 0) g_off[NN] = s[1023];
}
__global__ void k_fill(const void* ei, int E) {
    int e = blockIdx.x * blockDim.x + threadIdx.x;
    int tot = E + NN;
    if (e >= tot) return;
    int r, c;
    if (e < E) { r = ld_idx(ei, e); c = ld_idx(ei, (long long)E + e); }
    else { r = e - E; c = r; }
    int p = atomicAdd(&g_cur[c], 1);
    int idx = g_off[c] + p;
    g_edge[idx] = make_int2(r, __float_as_int(g_dinv[r] * g_dinv[c]));
}

// all 4 weights: W [K,512] fp32 -> Wt fp16 [512][K] (tiled transpose)
__global__ void k_wconv_all(const float* __restrict__ W1, const float* __restrict__ W2,
                            const float* __restrict__ W3, const float* __restrict__ W4,
                            __half* __restrict__ whB) {
    __shared__ float t[32][33];
    int l = blockIdx.z;
    const float* W = (l == 0) ? W1 : (l == 1) ? W2 : (l == 2) ? W3 : W4;
    int K = (l == 0) ? 256 : 512;
    int k0 = blockIdx.x * 32, n0 = blockIdx.y * 32;
    if (k0 >= K) return;
    __half* wh = whB + (size_t)l * 512 * 512;
    int tx = threadIdx.x, ty = threadIdx.y;
    t[ty][tx] = W[(size_t)(k0 + ty) * 512 + n0 + tx];
    __syncthreads();
    wh[(size_t)(n0 + ty) * K + k0 + tx] = __float2half_rn(t[tx][ty]);
}

// ---------------- SpMM: acc fp32, write fp16 ----------------
__device__ __forceinline__ uint32_t packh2(float a, float b) {
    __half2 t = __floats2half2_rn(a, b);
    return *(uint32_t*)&t;
}
// layer 1: fp32 input, FD=256, 64 threads
__global__ void k_spmm_f32in(const float* __restrict__ h, __half* __restrict__ af) {
    const int FD = 256, V = FD / 4;
    int node = blockIdx.x;
    int tid  = threadIdx.x;
    int s = g_off[node], e = g_off[node + 1];
    const float4* h4 = (const float4*)h;
    float4 acc = make_float4(0.f, 0.f, 0.f, 0.f);
    int i = s;
    for (; i + 4 <= e; i += 4) {
        int2 e0 = g_edge[i],     e1 = g_edge[i + 1];
        int2 e2 = g_edge[i + 2], e3 = g_edge[i + 3];
        float w0 = __int_as_float(e0.y), w1 = __int_as_float(e1.y);
        float w2 = __int_as_float(e2.y), w3 = __int_as_float(e3.y);
        float4 v0 = h4[(size_t)e0.x * V + tid];
        float4 v1 = h4[(size_t)e1.x * V + tid];
        float4 v2 = h4[(size_t)e2.x * V + tid];
        float4 v3 = h4[(size_t)e3.x * V + tid];
        acc.x += w0 * v0.x; acc.y += w0 * v0.y; acc.z += w0 * v0.z; acc.w += w0 * v0.w;
        acc.x += w1 * v1.x; acc.y += w1 * v1.y; acc.z += w1 * v1.z; acc.w += w1 * v1.w;
        acc.x += w2 * v2.x; acc.y += w2 * v2.y; acc.z += w2 * v2.z; acc.w += w2 * v2.w;
        acc.x += w3 * v3.x; acc.y += w3 * v3.y; acc.z += w3 * v3.z; acc.w += w3 * v3.w;
    }
    for (; i < e; i++) {
        int2 e0 = g_edge[i];
        float w = __int_as_float(e0.y);
        float4 v = h4[(size_t)e0.x * V + tid];
        acc.x += w * v.x; acc.y += w * v.y; acc.z += w * v.z; acc.w += w * v.w;
    }
    uint2 u;
    u.x = packh2(acc.x, acc.y);
    u.y = packh2(acc.z, acc.w);
    *(uint2*)(af + (size_t)node * FD + tid * 4) = u;
}
// layers 2-4: fp16 input, FD=512, 128 threads (8B gather per thread)
__global__ void k_spmm_f16in(const __half* __restrict__ h, __half* __restrict__ af) {
    const int FD = 512, V = FD / 4;                // uint2 = 4 halves
    int node = blockIdx.x;
    int tid  = threadIdx.x;
    int s = g_off[node], e = g_off[node + 1];
    const uint2* h4 = (const uint2*)h;
    float4 acc = make_float4(0.f, 0.f, 0.f, 0.f);
    int i = s;
    for (; i + 4 <= e; i += 4) {
        int2 e0 = g_edge[i],     e1 = g_edge[i + 1];
        int2 e2 = g_edge[i + 2], e3 = g_edge[i + 3];
        float w0 = __int_as_float(e0.y), w1 = __int_as_float(e1.y);
        float w2 = __int_as_float(e2.y), w3 = __int_as_float(e3.y);
        uint2 u0 = h4[(size_t)e0.x * V + tid];
        uint2 u1 = h4[(size_t)e1.x * V + tid];
        uint2 u2 = h4[(size_t)e2.x * V + tid];
        uint2 u3 = h4[(size_t)e3.x * V + tid];
        float2 a0 = __half22float2(*(__half2*)&u0.x), b0 = __half22float2(*(__half2*)&u0.y);
        float2 a1 = __half22float2(*(__half2*)&u1.x), b1 = __half22float2(*(__half2*)&u1.y);
        float2 a2 = __half22float2(*(__half2*)&u2.x), b2 = __half22float2(*(__half2*)&u2.y);
        float2 a3 = __half22float2(*(__half2*)&u3.x), b3 = __half22float2(*(__half2*)&u3.y);
        acc.x += w0 * a0.x; acc.y += w0 * a0.y; acc.z += w0 * b0.x; acc.w += w0 * b0.y;
        acc.x += w1 * a1.x; acc.y += w1 * a1.y; acc.z += w1 * b1.x; acc.w += w1 * b1.y;
        acc.x += w2 * a2.x; acc.y += w2 * a2.y; acc.z += w2 * b2.x; acc.w += w2 * b2.y;
        acc.x += w3 * a3.x; acc.y += w3 * a3.y; acc.z += w3 * b3.x; acc.w += w3 * b3.y;
    }
    for (; i < e; i++) {
        int2 e0 = g_edge[i];
        float w = __int_as_float(e0.y);
        uint2 u0 = h4[(size_t)e0.x * V + tid];
        float2 a0 = __half22float2(*(__half2*)&u0.x), b0 = __half22float2(*(__half2*)&u0.y);
        acc.x += w * a0.x; acc.y += w * a0.y; acc.z += w * b0.x; acc.w += w * b0.y;
    }
    uint2 u;
    u.x = packh2(acc.x, acc.y);
    u.y = packh2(acc.z, acc.w);
    *(uint2*)(af + (size_t)node * FD + tid * 4) = u;
}

// ---------------- HMMA helpers ----------------
__device__ __forceinline__ uint32_t smem_u32(const void* p) {
    uint32_t a;
    asm("{ .reg .u64 t; cvta.to.shared.u64 t, %1; cvt.u32.u64 %0, t; }" : "=r"(a) : "l"(p));
    return a;
}
#define LDSM_X4(r0, r1, r2, r3, addr) \
    asm volatile("ldmatrix.sync.aligned.m8n8.x4.shared.b16 {%0,%1,%2,%3}, [%4];" \
        : "=r"(r0), "=r"(r1), "=r"(r2), "=r"(r3) : "r"(addr))
#define MMA16816F(d, a0, a1, a2, a3, b0, b1) \
    asm volatile("mma.sync.aligned.m16n8k16.row.col.f32.f16.f16.f32 " \
        "{%0,%1,%2,%3}, {%4,%5,%6,%7}, {%8,%9}, {%0,%1,%2,%3};" \
        : "+f"((d)[0]), "+f"((d)[1]), "+f"((d)[2]), "+f"((d)[3]) \
        : "r"(a0), "r"(a1), "r"(a2), "r"(a3), "r"(b0), "r"(b1))
#define CP_ASYNC16(dst, src, sz) \
    asm volatile("cp.async.cg.shared.global [%0], [%1], 16, %2;" \
        :: "r"(dst), "l"(src), "r"(sz) : "memory")
#define CP_COMMIT() asm volatile("cp.async.commit_group;" ::: "memory")
#define CP_WAIT(n)  asm volatile("cp.async.wait_group %0;" :: "n"(n) : "memory")

// ---------------- fp16 single-pass HMMA GEMM, K-chunk 64, 2-stage -----------
// layers 1-3 (OUT16=1): h16 = relu(A @ Wh^T + bias) fp16
// layer 4   (OUT16=0): out = A @ Wh^T + bias fp32
#define SPAD 72   // padded smem row stride (fp16 elems) for 64-wide K chunk
template <int K, int OUT16>
__global__ void __launch_bounds__(256, 2)
k_gemm_mma(const __half* __restrict__ Af, const __half* __restrict__ Wh,
           const float* __restrict__ bias, void* __restrict__ Cout) {
    extern __shared__ __half sm[];
    const int M = NN;
    const int NC = K / 64;                        // 4 or 8
    const int TILE = 128 * SPAD;
    const int STAGE = 2 * TILE;                   // Af, Wh

    int tid = threadIdx.x;
    int wid = tid >> 5, lane = tid & 31;
    int wm = wid & 3, wn = wid >> 2;              // warp grid 4(M) x 2(N)
    int bx = blockIdx.x, by = blockIdx.y;

    float acc[2][8][4];
#pragma unroll
    for (int i = 0; i < 2; i++)
#pragma unroll
        for (int j = 0; j < 8; j++)
#pragma unroll
            for (int q = 0; q < 4; q++) acc[i][j][q] = 0.f;

    // 128 rows x 64 halves = 8 chunks(16B)/row = 1024 chunks/tile; 4 iters/tile
    auto stage_load = [&](int st, int k0) {
        __half* dst = sm + st * STAGE;
#pragma unroll
        for (int t = 0; t < 2; t++) {
            const __half* src = t ? Wh : Af;
            bool isA = (t == 0);
            int rowBase = isA ? by * 128 : bx * 128;
#pragma unroll
            for (int it = 0; it < 4; it++) {
                int idx = it * 256 + tid;
                int r = idx >> 3, kc = idx & 7;
                int gr = rowBase + r;
                uint32_t d = smem_u32(dst + t * TILE + r * SPAD + kc * 8);
                const __half* s = src + (size_t)gr * K + k0 + kc * 8;
                int sz = (!isA || gr < M) ? 16 : 0;
                CP_ASYNC16(d, s, sz);
            }
        }
    };

    stage_load(0, 0);
    CP_COMMIT();

    for (int i = 0; i < NC; i++) {
        if (i + 1 < NC) { stage_load((i + 1) & 1, (i + 1) * 64); CP_COMMIT(); }
        if (i + 1 < NC) CP_WAIT(1); else CP_WAIT(0);
        __syncthreads();

        __half* st = sm + (i & 1) * STAGE;
        uint32_t sAf = smem_u32(st);
        uint32_t sBh = smem_u32(st + TILE);

#pragma unroll
        for (int ks = 0; ks < 4; ks++) {
            int koff = ks * 16 + (lane >> 4) * 8;
            int arow = wm * 32 + (lane & 15);
            int brow = wn * 64 + (lane & 15);
            uint32_t ah[2][4];
#pragma unroll
            for (int mi = 0; mi < 2; mi++) {
                uint32_t ad = (uint32_t)(((arow + mi * 16) * SPAD + koff) * 2);
                LDSM_X4(ah[mi][0], ah[mi][1], ah[mi][2], ah[mi][3], sAf + ad);
            }
#pragma unroll
            for (int ni = 0; ni < 4; ni++) {
                uint32_t bd = (uint32_t)(((brow + ni * 16) * SPAD + koff) * 2);
                uint32_t bh[4];
                LDSM_X4(bh[0], bh[1], bh[2], bh[3], sBh + bd);
#pragma unroll
                for (int mi = 0; mi < 2; mi++) {
                    MMA16816F(acc[mi][ni * 2 + 0], ah[mi][0], ah[mi][1], ah[mi][2], ah[mi][3],
                              bh[0], bh[2]);
                    MMA16816F(acc[mi][ni * 2 + 1], ah[mi][0], ah[mi][1], ah[mi][2], ah[mi][3],
                              bh[1], bh[3]);
                }
            }
        }
        __syncthreads();
    }

    // epilogue
#pragma unroll
    for (int mi = 0; mi < 2; mi++) {
        int grow = by * 128 + wm * 32 + mi * 16 + (lane >> 2);
#pragma unroll
        for (int ni = 0; ni < 8; ni++) {
            int gcol = bx * 128 + wn * 64 + ni * 8 + (lane & 3) * 2;
            float bx0 = bias[gcol], bx1 = bias[gcol + 1];
            float2 v0, v1;
            v0.x = acc[mi][ni][0] + bx0; v0.y = acc[mi][ni][1] + bx1;
            v1.x = acc[mi][ni][2] + bx0; v1.y = acc[mi][ni][3] + bx1;
            if (OUT16) {
                v0.x = fmaxf(v0.x, 0.f); v0.y = fmaxf(v0.y, 0.f);
                v1.x = fmaxf(v1.x, 0.f); v1.y = fmaxf(v1.y, 0.f);
                __half* C16 = (__half*)Cout;
                if (grow < M)
                    *(__half2*)(C16 + (size_t)grow * 512 + gcol) = __floats2half2_rn(v0.x, v0.y);
                if (grow + 8 < M)
                    *(__half2*)(C16 + (size_t)(grow + 8) * 512 + gcol) = __floats2half2_rn(v1.x, v1.y);
            } else {
                float* C = (float*)Cout;
                if (grow < M)     *(float2*)(C + (size_t)grow * 512 + gcol) = v0;
                if (grow + 8 < M) *(float2*)(C + (size_t)(grow + 8) * 512 + gcol) = v1;
            }
        }
    }
}

// ---------------- launch ----------------
extern "C" void kernel_launch(void* const* d_in, const int* in_sizes, int n_in,
                              void* d_out, int out_size) {
    const float* x  = (const float*)d_in[0];
    const void*  ei = d_in[1];
    const float* W1 = (const float*)d_in[2];
    const float* b1 = (const float*)d_in[3];
    const float* W2 = (const float*)d_in[4];
    const float* b2 = (const float*)d_in[5];
    const float* W3 = (const float*)d_in[6];
    const float* b3 = (const float*)d_in[7];
    const float* W4 = (const float*)d_in[8];
    const float* b4 = (const float*)d_in[9];
    float* out = (float*)d_out;

    int E = in_sizes[1] / 2;

    __half *h16, *af, *wh;
    cudaGetSymbolAddress((void**)&h16, g_h16);
    cudaGetSymbolAddress((void**)&af,  g_af);
    cudaGetSymbolAddress((void**)&wh,  g_wh);

    const int GSMEM = 2 * 2 * 128 * SPAD * 2;   // 2 stages * 2 tiles = 73728 B
    static int attr_done = 0;
    if (!attr_done) {
        cudaFuncSetAttribute((const void*)k_gemm_mma<256, 1>, cudaFuncAttributeMaxDynamicSharedMemorySize, GSMEM);
        cudaFuncSetAttribute((const void*)k_gemm_mma<512, 1>, cudaFuncAttributeMaxDynamicSharedMemorySize, GSMEM);
        cudaFuncSetAttribute((const void*)k_gemm_mma<512, 0>, cudaFuncAttributeMaxDynamicSharedMemorySize, GSMEM);
        attr_done = 1;
    }

    // ---- preprocessing ----
    k_init<<<(NN + 127) / 128, 128>>>(ei, E);
    k_deg<<<(E + 255) / 256, 256>>>(ei, E);
    k_scan<<<1, 1024>>>();
    k_fill<<<(E + NN + 255) / 256, 256>>>(ei, E);
    k_wconv_all<<<dim3(16, 16, 4), dim3(32, 32)>>>(W1, W2, W3, W4, wh);

    dim3 ggrid(4, (NN + 127) / 128);

    // ---- layer 1 (K=256) ----
    k_spmm_f32in<<<NN, 64>>>(x, af);
    k_gemm_mma<256, 1><<<ggrid, 256, GSMEM>>>(af, wh + 0 * 512 * 512, b1, h16);
    // ---- layer 2 ----
    k_spmm_f16in<<<NN, 128>>>(h16, af);
    k_gemm_mma<512, 1><<<ggrid, 256, GSMEM>>>(af, wh + 1 * 512 * 512, b2, h16);
    // ---- layer 3 ----
    k_spmm_f16in<<<NN, 128>>>(h16, af);
    k_gemm_mma<512, 1><<<ggrid, 256, GSMEM>>>(af, wh + 2 * 512 * 512, b3, h16);
    // ---- layer 4 (no relu, fp32 to d_out) ----
    k_spmm_f16in<<<NN, 128>>>(h16, af);
    k_gemm_mma<512, 0><<<ggrid, 256, GSMEM>>>(af, wh + 3 * 512 * 512, b4, out);
}